// round 13
// baseline (speedup 1.0000x reference)
#include <cuda_runtime.h>
#include <cuda_fp16.h>

#define HW 4096

// Scratch: Q, K, V maps (B=2, C=128, H*W=4096), fp32
__device__ float g_Q[2 * 128 * HW];
__device__ float g_K[2 * 128 * HW];
__device__ float g_V[2 * 128 * HW];

// ---------------------------------------------------------------------------
// Kernel 1: fused 1x1-conv GEMMs.  out[o,s] = sum_c W[c,o] * X[c,s]
// ot: 0 -> Q (wq, fm_t1), 1 -> K (wk, fm_t0), 2 -> V (wv, fm_t0).
// Block tile 128o x 64s -> 384 blocks, 256 thr, 8x4 microtile.
// W is transposed into smem in the prologue via two 32x32 XOR-swizzled
// staging tiles living in the (not-yet-used) X double-buffer region.
// ---------------------------------------------------------------------------
__global__ __launch_bounds__(256, 3) void qkv_kernel(
    const float* __restrict__ fm,
    const float* __restrict__ wq,
    const float* __restrict__ wk,
    const float* __restrict__ wv)
{
    extern __shared__ float sm[];
    float* Wt = sm;                   // [c][o] : 128*128
    float* Xt = sm + 16384;           // [2][16][64]  (also transpose staging)

    const int tid = threadIdx.x;
    const int ot  = blockIdx.y;        // 0..2
    const int b   = blockIdx.z;        // 0..1
    const int s0  = blockIdx.x << 6;   // 64 stiles of 64

    const float* Wg = (ot == 0) ? wq : (ot == 1) ? wk : wv;
    const float* X  = fm + (size_t)(b * 256 + (ot == 0 ? 128 : 0)) * HW;
    float* OUT      = (ot == 0) ? g_Q : (ot == 1) ? g_K : g_V;

    // ---- inline transpose: W[o][c] (global) -> Wt[c][o] (smem) ----
    {
        const int ttx = tid & 31;          // lane
        const int tty = tid >> 5;          // warp 0..7
        float* st0 = Xt;                   // 32x32 swizzled
        float* st1 = Xt + 1024;
        for (int it = 0; it < 8; it++) {
#pragma unroll
            for (int p = 0; p < 2; p++) {
                const int st = it * 2 + p;
                const int bo = (st >> 2) << 5;   // o tile base
                const int bc = (st & 3) << 5;    // c tile base
                float* stg = p ? st1 : st0;
#pragma unroll
                for (int i = 0; i < 4; i++) {
                    const int r = tty * 4 + i;   // o_local
                    stg[r * 32 + (ttx ^ r)] = Wg[(bo + r) * 128 + bc + ttx];
                }
            }
            __syncthreads();
#pragma unroll
            for (int p = 0; p < 2; p++) {
                const int st = it * 2 + p;
                const int bo = (st >> 2) << 5;
                const int bc = (st & 3) << 5;
                const float* stg = p ? st1 : st0;
#pragma unroll
                for (int i = 0; i < 4; i++) {
                    const int cl = tty * 4 + i;  // c_local
                    Wt[(bc + cl) * 128 + bo + ttx] = stg[ttx * 32 + (cl ^ ttx)];
                }
            }
            __syncthreads();
        }
    }

    // X chunk-load coordinates (one float4 per thread per chunk)
    const int xc = tid >> 4;            // 0..15 (c within chunk)
    const int xs = (tid & 15) << 2;     // 0..60 (s quad)

    float4 xr = *(const float4*)(X + (size_t)xc * HW + s0 + xs);
    *(float4*)&Xt[xc * 64 + xs] = xr;
    __syncthreads();

    const int to = (tid >> 4) << 3;     // 0..120 (o base)
    const int ts = (tid & 15) << 2;     // 0..60  (s base)

    float acc[8][4];
#pragma unroll
    for (int i = 0; i < 8; i++)
#pragma unroll
        for (int j = 0; j < 4; j++) acc[i][j] = 0.f;

    for (int k = 0; k < 8; k++) {
        const int buf = k & 1;
        if (k < 7)   // prefetch next X chunk
            xr = *(const float4*)(X + (size_t)((k + 1) * 16 + xc) * HW + s0 + xs);

        const float* Wc = Wt + k * 16 * 128;
        const float* Xc = Xt + buf * 1024;
#pragma unroll
        for (int c = 0; c < 16; c++) {
            const float4 a0 = *(const float4*)(Wc + c * 128 + to);
            const float4 a1 = *(const float4*)(Wc + c * 128 + to + 4);
            const float4 x0 = *(const float4*)(Xc + c * 64 + ts);
            const float av[8] = {a0.x, a0.y, a0.z, a0.w, a1.x, a1.y, a1.z, a1.w};
            const float xv[4] = {x0.x, x0.y, x0.z, x0.w};
#pragma unroll
            for (int i = 0; i < 8; i++)
#pragma unroll
                for (int j = 0; j < 4; j++)
                    acc[i][j] += av[i] * xv[j];
        }
        if (k < 7)
            *(float4*)&Xt[(buf ^ 1) * 1024 + xc * 64 + xs] = xr;
        __syncthreads();
    }

    float* Ob = OUT + (size_t)(b * 128 + to) * HW + s0 + ts;
#pragma unroll
    for (int i = 0; i < 8; i++)
        *(float4*)(Ob + (size_t)i * HW) =
            make_float4(acc[i][0], acc[i][1], acc[i][2], acc[i][3]);
}

// ---------------------------------------------------------------------------
// Kernel 2: fused window attention + row/col refine.
// One thread per position, all 16 group-channels (round-1 structure: no
// duplicated exp/softmax work). K tile in fp32 (score precision), V tile in
// fp16 half2-packed (output error ~1e-4, 10x under tolerance). smem 62.3KB
// -> 3 blocks (12 warps) per SM instead of 2 blocks (8 warps) at full fp32.
// Direct-exp softmax (shift-invariant; scores far from fp32 overflow).
// ---------------------------------------------------------------------------
#define HR 22
#define HC 30
#define C4STR (HR * HC)       // 660
#define KT4   (4 * C4STR)     // 2640 float4 (K, 4 ch-quad planes)
#define VT4   (2 * C4STR)     // 1320 uint4  (V, 2 ch-octet half8 planes)

__device__ __forceinline__ float dot16(const float* q, float4 k0, float4 k1,
                                       float4 k2, float4 k3)
{
    float s;
    s  = q[0]  * k0.x + q[1]  * k0.y + q[2]  * k0.z + q[3]  * k0.w;
    s += q[4]  * k1.x + q[5]  * k1.y + q[6]  * k1.z + q[7]  * k1.w;
    s += q[8]  * k2.x + q[9]  * k2.y + q[10] * k2.z + q[11] * k2.w;
    s += q[12] * k3.x + q[13] * k3.y + q[14] * k3.z + q[15] * k3.w;
    return s;
}

__device__ __forceinline__ void accv(float* a, float p, uint4 va, uint4 vb)
{
    const float2 f0 = __half22float2(*(const __half2*)&va.x);
    const float2 f1 = __half22float2(*(const __half2*)&va.y);
    const float2 f2 = __half22float2(*(const __half2*)&va.z);
    const float2 f3 = __half22float2(*(const __half2*)&va.w);
    const float2 f4 = __half22float2(*(const __half2*)&vb.x);
    const float2 f5 = __half22float2(*(const __half2*)&vb.y);
    const float2 f6 = __half22float2(*(const __half2*)&vb.z);
    const float2 f7 = __half22float2(*(const __half2*)&vb.w);
    a[0]  += p * f0.x;  a[1]  += p * f0.y;
    a[2]  += p * f1.x;  a[3]  += p * f1.y;
    a[4]  += p * f2.x;  a[5]  += p * f2.y;
    a[6]  += p * f3.x;  a[7]  += p * f3.y;
    a[8]  += p * f4.x;  a[9]  += p * f4.y;
    a[10] += p * f5.x;  a[11] += p * f5.y;
    a[12] += p * f6.x;  a[13] += p * f6.y;
    a[14] += p * f7.x;  a[15] += p * f7.y;
}

template <int NT, typename F>
__device__ __forceinline__ void attn_branch(
    F tap,
    const float4* __restrict__ Kt, const uint4* __restrict__ Vt,
    const float* q, float* outv)
{
    float l = 0.f;
    float a[16];
#pragma unroll
    for (int c = 0; c < 16; c++) a[c] = 0.f;

#pragma unroll
    for (int t = 0; t < NT; t++) {
        int off; float s;
        tap(t, off, s);
        const float4 k0 = Kt[off];
        const float4 k1 = Kt[C4STR + off];
        const float4 k2 = Kt[2 * C4STR + off];
        const float4 k3 = Kt[3 * C4STR + off];
        s += dot16(q, k0, k1, k2, k3);
        const float p = __expf(s);
        l += p;
        accv(a, p, Vt[off], Vt[C4STR + off]);
    }
    const float inv = 1.f / l;
#pragma unroll
    for (int c = 0; c < 16; c++) outv[c] += a[c] * inv;
}

__global__ __launch_bounds__(128, 3) void attn_kernel(
    const float* __restrict__ rel_h,
    const float* __restrict__ rel_w,
    float* __restrict__ out)
{
    extern __shared__ float4 sm4[];
    float4* Kt  = sm4;                          // fp32 K: 4 planes x 660
    uint4*  Vt  = (uint4*)(sm4 + KT4);          // fp16 V: 2 planes x 660
    float* rels = (float*)(sm4 + KT4 + VT4);    // [16*7]

    const int tid = threadIdx.x;
    const int tx = tid & 15, ty = tid >> 4;
    const int w0 = blockIdx.x << 4;             // 4 tiles of 16
    const int h0 = blockIdx.y << 3;             // 8 tiles of 8
    const int b  = blockIdx.z >> 3;
    const int g  = blockIdx.z & 7;
    const int cb = g << 4;

    if (tid < 112) {
        const int c = tid / 7, i = tid % 7;
        rels[tid] = (g < 4) ? rel_h[(cb + c) * 7 + i]
                            : rel_w[(cb + c - 64) * 7 + i];
    }

    const float* Kg = g_K + (size_t)(b * 128 + cb) * HW;
    const float* Vg = g_V + (size_t)(b * 128 + cb) * HW;

    // K tile: fp32, 4 channel-quad planes (zero outside image = padding)
    for (int idx = tid; idx < KT4; idx += 128) {
        const int c4  = idx / C4STR;
        const int rem = idx - c4 * C4STR;
        const int r   = rem / HC;
        const int cc  = rem - r * HC;
        const int h = h0 - 7 + r;
        const int w = w0 - 7 + cc;
        float4 kv = make_float4(0.f, 0.f, 0.f, 0.f);
        if ((unsigned)h < 64u && (unsigned)w < 64u) {
            const size_t base = (size_t)(c4 * 4) * HW + h * 64 + w;
            kv.x = Kg[base];          kv.y = Kg[base + HW];
            kv.z = Kg[base + 2 * HW]; kv.w = Kg[base + 3 * HW];
        }
        Kt[idx] = kv;
    }
    // V tile: fp16 half2-packed, 2 channel-octet planes
    for (int idx = tid; idx < VT4; idx += 128) {
        const int p   = idx / C4STR;            // 0: ch0-7, 1: ch8-15
        const int rem = idx - p * C4STR;
        const int r   = rem / HC;
        const int cc  = rem - r * HC;
        const int h = h0 - 7 + r;
        const int w = w0 - 7 + cc;
        uint4 u = make_uint4(0u, 0u, 0u, 0u);
        if ((unsigned)h < 64u && (unsigned)w < 64u) {
            const size_t base = (size_t)(p * 8) * HW + h * 64 + w;
            __half2 h0v = __floats2half2_rn(Vg[base],          Vg[base + HW]);
            __half2 h1v = __floats2half2_rn(Vg[base + 2 * HW], Vg[base + 3 * HW]);
            __half2 h2v = __floats2half2_rn(Vg[base + 4 * HW], Vg[base + 5 * HW]);
            __half2 h3v = __floats2half2_rn(Vg[base + 6 * HW], Vg[base + 7 * HW]);
            u.x = *(unsigned*)&h0v; u.y = *(unsigned*)&h1v;
            u.z = *(unsigned*)&h2v; u.w = *(unsigned*)&h3v;
        }
        Vt[idx] = u;
    }
    __syncthreads();

    const int h = h0 + ty, w = w0 + tx;

    float q[16];
    const float* Qg = g_Q + (size_t)(b * 128 + cb) * HW + h * 64 + w;
#pragma unroll
    for (int c = 0; c < 16; c++) q[c] = Qg[(size_t)c * HW];

    // rel bias scores in registers (all loops fully unrolled)
    float rp[7];
#pragma unroll
    for (int i = 0; i < 7; i++) {
        float s = 0.f;
#pragma unroll
        for (int c = 0; c < 16; c++) s += q[c] * rels[c * 7 + i];
        rp[i] = s;
    }
    const bool useI = (g < 4);

    float outv[16];
#pragma unroll
    for (int c = 0; c < 16; c++) outv[c] = 0.f;

    // main 7x7 window attention (score = <q,k> + rel)
    attn_branch<49>([&](int t, int& off, float& s) {
        const int i = t / 7, j = t - i * 7;
        off = (ty + 4 + i) * HC + (tx + 4 + j);
        s = useI ? rp[i] : rp[j];
    }, Kt, Vt, q, outv);

    // row refine: 15 taps along w
    attn_branch<15>([&](int t, int& off, float& s) {
        off = (ty + 7) * HC + (tx + t);
        s = 0.f;
    }, Kt, Vt, q, outv);

    // col refine: 15 taps along h
    attn_branch<15>([&](int t, int& off, float& s) {
        off = (ty + t) * HC + (tx + 7);
        s = 0.f;
    }, Kt, Vt, q, outv);

    float* Og = out + (size_t)(b * 128 + cb) * HW + h * 64 + w;
#pragma unroll
    for (int c = 0; c < 16; c++) Og[(size_t)c * HW] = outv[c];
}

// ---------------------------------------------------------------------------
extern "C" void kernel_launch(void* const* d_in, const int* in_sizes, int n_in,
                              void* d_out, int out_size)
{
    const float* fm = (const float*)d_in[0];
    const float* wq = (const float*)d_in[1];
    const float* wk = (const float*)d_in[2];
    const float* wv = (const float*)d_in[3];
    const float* rh = (const float*)d_in[4];
    const float* rw = (const float*)d_in[5];
    float* out = (float*)d_out;

    cudaFuncSetAttribute(qkv_kernel,  cudaFuncAttributeMaxDynamicSharedMemorySize, 73728);
    cudaFuncSetAttribute(attn_kernel, cudaFuncAttributeMaxDynamicSharedMemorySize, 65536);
    cudaFuncSetAttribute(qkv_kernel,  cudaFuncAttributePreferredSharedMemoryCarveout, 100);
    cudaFuncSetAttribute(attn_kernel, cudaFuncAttributePreferredSharedMemoryCarveout, 100);

    qkv_kernel<<<dim3(64, 3, 2), 256, 73728>>>(fm, wq, wk, wv);

    // K fp32 (42240B) + V fp16 (21120B) + rels (448B) = 63808B -> 3 blocks/SM
    const int attn_smem = KT4 * 16 + VT4 * 16 + 112 * 4;
    attn_kernel<<<dim3(4, 8, 16), 128, attn_smem>>>(rh, rw, out);
}

// round 15
// speedup vs baseline: 1.2622x; 1.2622x over previous
#include <cuda_runtime.h>
#include <cuda_fp16.h>

#define HW 4096

// Scratch: Q, K, V maps (B=2, C=128, H*W=4096), fp32
__device__ float g_Q[2 * 128 * HW];
__device__ float g_K[2 * 128 * HW];
__device__ float g_V[2 * 128 * HW];

// ---------------------------------------------------------------------------
// Kernel 1: fused 1x1-conv GEMMs.  out[o,s] = sum_c W[c,o] * X[c,s]
// ot: 0 -> Q (wq, fm_t1), 1 -> K (wk, fm_t0), 2 -> V (wv, fm_t0).
// Block tile 128o x 64s -> 384 blocks, 256 thr, 8x4 microtile.
// W is transposed into smem in the prologue via two 32x32 XOR-swizzled
// staging tiles living in the (not-yet-used) X double-buffer region.
// ---------------------------------------------------------------------------
__global__ __launch_bounds__(256, 3) void qkv_kernel(
    const float* __restrict__ fm,
    const float* __restrict__ wq,
    const float* __restrict__ wk,
    const float* __restrict__ wv)
{
    extern __shared__ float sm[];
    float* Wt = sm;                   // [c][o] : 128*128
    float* Xt = sm + 16384;           // [2][16][64]  (also transpose staging)

    const int tid = threadIdx.x;
    const int ot  = blockIdx.y;        // 0..2
    const int b   = blockIdx.z;        // 0..1
    const int s0  = blockIdx.x << 6;   // 64 stiles of 64

    const float* Wg = (ot == 0) ? wq : (ot == 1) ? wk : wv;
    const float* X  = fm + (size_t)(b * 256 + (ot == 0 ? 128 : 0)) * HW;
    float* OUT      = (ot == 0) ? g_Q : (ot == 1) ? g_K : g_V;

    // ---- inline transpose: W[o][c] (global) -> Wt[c][o] (smem) ----
    {
        const int ttx = tid & 31;          // lane
        const int tty = tid >> 5;          // warp 0..7
        float* st0 = Xt;                   // 32x32 swizzled
        float* st1 = Xt + 1024;
        for (int it = 0; it < 8; it++) {
#pragma unroll
            for (int p = 0; p < 2; p++) {
                const int st = it * 2 + p;
                const int bo = (st >> 2) << 5;   // o tile base
                const int bc = (st & 3) << 5;    // c tile base
                float* stg = p ? st1 : st0;
#pragma unroll
                for (int i = 0; i < 4; i++) {
                    const int r = tty * 4 + i;   // o_local
                    stg[r * 32 + (ttx ^ r)] = Wg[(bo + r) * 128 + bc + ttx];
                }
            }
            __syncthreads();
#pragma unroll
            for (int p = 0; p < 2; p++) {
                const int st = it * 2 + p;
                const int bo = (st >> 2) << 5;
                const int bc = (st & 3) << 5;
                const float* stg = p ? st1 : st0;
#pragma unroll
                for (int i = 0; i < 4; i++) {
                    const int cl = tty * 4 + i;  // c_local
                    Wt[(bc + cl) * 128 + bo + ttx] = stg[ttx * 32 + (cl ^ ttx)];
                }
            }
            __syncthreads();
        }
    }

    // X chunk-load coordinates (one float4 per thread per chunk)
    const int xc = tid >> 4;            // 0..15 (c within chunk)
    const int xs = (tid & 15) << 2;     // 0..60 (s quad)

    float4 xr = *(const float4*)(X + (size_t)xc * HW + s0 + xs);
    *(float4*)&Xt[xc * 64 + xs] = xr;
    __syncthreads();

    const int to = (tid >> 4) << 3;     // 0..120 (o base)
    const int ts = (tid & 15) << 2;     // 0..60  (s base)

    float acc[8][4];
#pragma unroll
    for (int i = 0; i < 8; i++)
#pragma unroll
        for (int j = 0; j < 4; j++) acc[i][j] = 0.f;

    for (int k = 0; k < 8; k++) {
        const int buf = k & 1;
        if (k < 7)   // prefetch next X chunk
            xr = *(const float4*)(X + (size_t)((k + 1) * 16 + xc) * HW + s0 + xs);

        const float* Wc = Wt + k * 16 * 128;
        const float* Xc = Xt + buf * 1024;
#pragma unroll
        for (int c = 0; c < 16; c++) {
            const float4 a0 = *(const float4*)(Wc + c * 128 + to);
            const float4 a1 = *(const float4*)(Wc + c * 128 + to + 4);
            const float4 x0 = *(const float4*)(Xc + c * 64 + ts);
            const float av[8] = {a0.x, a0.y, a0.z, a0.w, a1.x, a1.y, a1.z, a1.w};
            const float xv[4] = {x0.x, x0.y, x0.z, x0.w};
#pragma unroll
            for (int i = 0; i < 8; i++)
#pragma unroll
                for (int j = 0; j < 4; j++)
                    acc[i][j] += av[i] * xv[j];
        }
        if (k < 7)
            *(float4*)&Xt[(buf ^ 1) * 1024 + xc * 64 + xs] = xr;
        __syncthreads();
    }

    float* Ob = OUT + (size_t)(b * 128 + to) * HW + s0 + ts;
#pragma unroll
    for (int i = 0; i < 8; i++)
        *(float4*)(Ob + (size_t)i * HW) =
            make_float4(acc[i][0], acc[i][1], acc[i][2], acc[i][3]);
}

// ---------------------------------------------------------------------------
// Kernel 2: fused window attention + row/col refine.
// COMPACT CODE: runtime outer loops (#pragma unroll 1) + unrolled 7-tap
// inner loop. Evidence from rounds 1/10/13: fully-unrolled bodies (35-64KB
// SASS) stream the I$ and cap issue at ~29% regardless of occupancy; the
// compact round-1 kernel was fastest. The rel-indexed window dimension is
// placed on the inner (unrolled) loop per useI so rp[] stays in registers
// with static indexing. Direct-exp softmax (shift-invariant; validated),
// K fp32 / V fp16 in smem -> 63.8KB -> 3 blocks (12 warps) per SM.
// ---------------------------------------------------------------------------
#define HR 22
#define HC 30
#define C4STR (HR * HC)       // 660
#define KT4   (4 * C4STR)     // 2640 float4 (K, 4 ch-quad planes)
#define VT4   (2 * C4STR)     // 1320 uint4  (V, 2 ch-octet half8 planes)

// one attention tap: score = <q,k16> + rel; p = exp(score); l += p; a += p*V
__device__ __forceinline__ void tap16(
    int off, float rel, float& l, float* a,
    const float4* __restrict__ Kt, const uint4* __restrict__ Vt,
    const float* q)
{
    const float4 k0 = Kt[off];
    const float4 k1 = Kt[C4STR + off];
    const float4 k2 = Kt[2 * C4STR + off];
    const float4 k3 = Kt[3 * C4STR + off];
    float s = rel;
    s += q[0]  * k0.x + q[1]  * k0.y + q[2]  * k0.z + q[3]  * k0.w;
    s += q[4]  * k1.x + q[5]  * k1.y + q[6]  * k1.z + q[7]  * k1.w;
    s += q[8]  * k2.x + q[9]  * k2.y + q[10] * k2.z + q[11] * k2.w;
    s += q[12] * k3.x + q[13] * k3.y + q[14] * k3.z + q[15] * k3.w;
    const float p = __expf(s);
    l += p;
    const uint4 va = Vt[off];
    const uint4 vb = Vt[C4STR + off];
    const float2 f0 = __half22float2(*(const __half2*)&va.x);
    const float2 f1 = __half22float2(*(const __half2*)&va.y);
    const float2 f2 = __half22float2(*(const __half2*)&va.z);
    const float2 f3 = __half22float2(*(const __half2*)&va.w);
    const float2 f4 = __half22float2(*(const __half2*)&vb.x);
    const float2 f5 = __half22float2(*(const __half2*)&vb.y);
    const float2 f6 = __half22float2(*(const __half2*)&vb.z);
    const float2 f7 = __half22float2(*(const __half2*)&vb.w);
    a[0]  += p * f0.x;  a[1]  += p * f0.y;
    a[2]  += p * f1.x;  a[3]  += p * f1.y;
    a[4]  += p * f2.x;  a[5]  += p * f2.y;
    a[6]  += p * f3.x;  a[7]  += p * f3.y;
    a[8]  += p * f4.x;  a[9]  += p * f4.y;
    a[10] += p * f5.x;  a[11] += p * f5.y;
    a[12] += p * f6.x;  a[13] += p * f6.y;
    a[14] += p * f7.x;  a[15] += p * f7.y;
}

__global__ __launch_bounds__(128, 3) void attn_kernel(
    const float* __restrict__ rel_h,
    const float* __restrict__ rel_w,
    float* __restrict__ out)
{
    extern __shared__ float4 sm4[];
    float4* Kt  = sm4;                          // fp32 K: 4 planes x 660
    uint4*  Vt  = (uint4*)(sm4 + KT4);          // fp16 V: 2 planes x 660
    float* rels = (float*)(sm4 + KT4 + VT4);    // [16*7]

    const int tid = threadIdx.x;
    const int tx = tid & 15, ty = tid >> 4;
    const int w0 = blockIdx.x << 4;             // 4 tiles of 16
    const int h0 = blockIdx.y << 3;             // 8 tiles of 8
    const int b  = blockIdx.z >> 3;
    const int g  = blockIdx.z & 7;
    const int cb = g << 4;

    if (tid < 112) {
        const int c = tid / 7, i = tid % 7;
        rels[tid] = (g < 4) ? rel_h[(cb + c) * 7 + i]
                            : rel_w[(cb + c - 64) * 7 + i];
    }

    const float* Kg = g_K + (size_t)(b * 128 + cb) * HW;
    const float* Vg = g_V + (size_t)(b * 128 + cb) * HW;

    // K tile: fp32, 4 channel-quad planes (zero outside image = padding)
    for (int idx = tid; idx < KT4; idx += 128) {
        const int c4  = idx / C4STR;
        const int rem = idx - c4 * C4STR;
        const int r   = rem / HC;
        const int cc  = rem - r * HC;
        const int h = h0 - 7 + r;
        const int w = w0 - 7 + cc;
        float4 kv = make_float4(0.f, 0.f, 0.f, 0.f);
        if ((unsigned)h < 64u && (unsigned)w < 64u) {
            const size_t base = (size_t)(c4 * 4) * HW + h * 64 + w;
            kv.x = Kg[base];          kv.y = Kg[base + HW];
            kv.z = Kg[base + 2 * HW]; kv.w = Kg[base + 3 * HW];
        }
        Kt[idx] = kv;
    }
    // V tile: fp16 half2-packed, 2 channel-octet planes
    for (int idx = tid; idx < VT4; idx += 128) {
        const int p   = idx / C4STR;            // 0: ch0-7, 1: ch8-15
        const int rem = idx - p * C4STR;
        const int r   = rem / HC;
        const int cc  = rem - r * HC;
        const int h = h0 - 7 + r;
        const int w = w0 - 7 + cc;
        uint4 u = make_uint4(0u, 0u, 0u, 0u);
        if ((unsigned)h < 64u && (unsigned)w < 64u) {
            const size_t base = (size_t)(p * 8) * HW + h * 64 + w;
            __half2 h0v = __floats2half2_rn(Vg[base],          Vg[base + HW]);
            __half2 h1v = __floats2half2_rn(Vg[base + 2 * HW], Vg[base + 3 * HW]);
            __half2 h2v = __floats2half2_rn(Vg[base + 4 * HW], Vg[base + 5 * HW]);
            __half2 h3v = __floats2half2_rn(Vg[base + 6 * HW], Vg[base + 7 * HW]);
            u.x = *(unsigned*)&h0v; u.y = *(unsigned*)&h1v;
            u.z = *(unsigned*)&h2v; u.w = *(unsigned*)&h3v;
        }
        Vt[idx] = u;
    }
    __syncthreads();

    const int h = h0 + ty, w = w0 + tx;

    float q[16];
    const float* Qg = g_Q + (size_t)(b * 128 + cb) * HW + h * 64 + w;
#pragma unroll
    for (int c = 0; c < 16; c++) q[c] = Qg[(size_t)c * HW];

    // rel bias scores in registers (this loop is fully unrolled: tiny)
    float rp[7];
#pragma unroll
    for (int i = 0; i < 7; i++) {
        float s = 0.f;
#pragma unroll
        for (int c = 0; c < 16; c++) s += q[c] * rels[c * 7 + i];
        rp[i] = s;
    }

    float outv[16];
#pragma unroll
    for (int c = 0; c < 16; c++) outv[c] = 0.f;

    float l;
    float a[16];

    // ---- main 7x7 window (score = <q,k> + rel) ----
    // rel-indexed dim on the inner UNROLLED loop -> rp[] static indexing;
    // outer loop kept runtime (#pragma unroll 1) for compact code.
    l = 0.f;
#pragma unroll
    for (int c = 0; c < 16; c++) a[c] = 0.f;
    if (g < 4) {
        // rel indexed by window row i -> inner loop over i (stride HC)
#pragma unroll 1
        for (int j = 0; j < 7; j++) {
            const int off0 = (ty + 4) * HC + (tx + 4 + j);
#pragma unroll
            for (int i = 0; i < 7; i++)
                tap16(off0 + i * HC, rp[i], l, a, Kt, Vt, q);
        }
    } else {
        // rel indexed by window col j -> inner loop over j (stride 1)
#pragma unroll 1
        for (int i = 0; i < 7; i++) {
            const int off0 = (ty + 4 + i) * HC + (tx + 4);
#pragma unroll
            for (int j = 0; j < 7; j++)
                tap16(off0 + j, rp[j], l, a, Kt, Vt, q);
        }
    }
    {
        const float inv = 1.f / l;
#pragma unroll
        for (int c = 0; c < 16; c++) outv[c] += a[c] * inv;
    }

    // ---- row refine: 15 taps along w ----
    l = 0.f;
#pragma unroll
    for (int c = 0; c < 16; c++) a[c] = 0.f;
#pragma unroll 1
    for (int t = 0; t < 15; t++)
        tap16((ty + 7) * HC + (tx + t), 0.f, l, a, Kt, Vt, q);
    {
        const float inv = 1.f / l;
#pragma unroll
        for (int c = 0; c < 16; c++) outv[c] += a[c] * inv;
    }

    // ---- col refine: 15 taps along h ----
    l = 0.f;
#pragma unroll
    for (int c = 0; c < 16; c++) a[c] = 0.f;
#pragma unroll 1
    for (int t = 0; t < 15; t++)
        tap16((ty + t) * HC + (tx + 7), 0.f, l, a, Kt, Vt, q);
    {
        const float inv = 1.f / l;
#pragma unroll
        for (int c = 0; c < 16; c++) outv[c] += a[c] * inv;
    }

    float* Og = out + (size_t)(b * 128 + cb) * HW + h * 64 + w;
#pragma unroll
    for (int c = 0; c < 16; c++) Og[(size_t)c * HW] = outv[c];
}

// ---------------------------------------------------------------------------
extern "C" void kernel_launch(void* const* d_in, const int* in_sizes, int n_in,
                              void* d_out, int out_size)
{
    const float* fm = (const float*)d_in[0];
    const float* wq = (const float*)d_in[1];
    const float* wk = (const float*)d_in[2];
    const float* wv = (const float*)d_in[3];
    const float* rh = (const float*)d_in[4];
    const float* rw = (const float*)d_in[5];
    float* out = (float*)d_out;

    cudaFuncSetAttribute(qkv_kernel,  cudaFuncAttributeMaxDynamicSharedMemorySize, 73728);
    cudaFuncSetAttribute(attn_kernel, cudaFuncAttributeMaxDynamicSharedMemorySize, 65536);
    cudaFuncSetAttribute(qkv_kernel,  cudaFuncAttributePreferredSharedMemoryCarveout, 100);
    cudaFuncSetAttribute(attn_kernel, cudaFuncAttributePreferredSharedMemoryCarveout, 100);

    qkv_kernel<<<dim3(64, 3, 2), 256, 73728>>>(fm, wq, wk, wv);

    // K fp32 (42240B) + V fp16 (21120B) + rels (448B) = 63808B -> 3 blocks/SM
    const int attn_smem = KT4 * 16 + VT4 * 16 + 112 * 4;
    attn_kernel<<<dim3(4, 8, 16), 128, attn_smem>>>(rh, rw, out);
}

// round 16
// speedup vs baseline: 1.3909x; 1.1020x over previous
#include <cuda_runtime.h>
#include <cuda_fp16.h>

#define HW 4096

// Scratch: Q, K, V maps (B=2, C=128, H*W=4096), fp32
__device__ float g_Q[2 * 128 * HW];
__device__ float g_K[2 * 128 * HW];
__device__ float g_V[2 * 128 * HW];

// ---------------------------------------------------------------------------
// Kernel 1: fused 1x1-conv GEMMs.  out[o,s] = sum_c W[c,o] * X[c,s]
// ot: 0 -> Q (wq, fm_t1), 1 -> K (wk, fm_t0), 2 -> V (wv, fm_t0).
// Block tile 128o x 64s -> 384 blocks, 256 thr, 8x4 microtile.
// W is transposed into smem in the prologue via two 32x32 XOR-swizzled
// staging tiles living in the (not-yet-used) X double-buffer region.
// ---------------------------------------------------------------------------
__global__ __launch_bounds__(256, 3) void qkv_kernel(
    const float* __restrict__ fm,
    const float* __restrict__ wq,
    const float* __restrict__ wk,
    const float* __restrict__ wv)
{
    extern __shared__ float sm[];
    float* Wt = sm;                   // [c][o] : 128*128
    float* Xt = sm + 16384;           // [2][16][64]  (also transpose staging)

    const int tid = threadIdx.x;
    const int ot  = blockIdx.y;        // 0..2
    const int b   = blockIdx.z;        // 0..1
    const int s0  = blockIdx.x << 6;   // 64 stiles of 64

    const float* Wg = (ot == 0) ? wq : (ot == 1) ? wk : wv;
    const float* X  = fm + (size_t)(b * 256 + (ot == 0 ? 128 : 0)) * HW;
    float* OUT      = (ot == 0) ? g_Q : (ot == 1) ? g_K : g_V;

    // ---- inline transpose: W[o][c] (global) -> Wt[c][o] (smem) ----
    {
        const int ttx = tid & 31;          // lane
        const int tty = tid >> 5;          // warp 0..7
        float* st0 = Xt;                   // 32x32 swizzled
        float* st1 = Xt + 1024;
        for (int it = 0; it < 8; it++) {
#pragma unroll
            for (int p = 0; p < 2; p++) {
                const int st = it * 2 + p;
                const int bo = (st >> 2) << 5;   // o tile base
                const int bc = (st & 3) << 5;    // c tile base
                float* stg = p ? st1 : st0;
#pragma unroll
                for (int i = 0; i < 4; i++) {
                    const int r = tty * 4 + i;   // o_local
                    stg[r * 32 + (ttx ^ r)] = Wg[(bo + r) * 128 + bc + ttx];
                }
            }
            __syncthreads();
#pragma unroll
            for (int p = 0; p < 2; p++) {
                const int st = it * 2 + p;
                const int bo = (st >> 2) << 5;
                const int bc = (st & 3) << 5;
                const float* stg = p ? st1 : st0;
#pragma unroll
                for (int i = 0; i < 4; i++) {
                    const int cl = tty * 4 + i;  // c_local
                    Wt[(bc + cl) * 128 + bo + ttx] = stg[ttx * 32 + (cl ^ ttx)];
                }
            }
            __syncthreads();
        }
    }

    // X chunk-load coordinates (one float4 per thread per chunk)
    const int xc = tid >> 4;            // 0..15 (c within chunk)
    const int xs = (tid & 15) << 2;     // 0..60 (s quad)

    float4 xr = *(const float4*)(X + (size_t)xc * HW + s0 + xs);
    *(float4*)&Xt[xc * 64 + xs] = xr;
    __syncthreads();

    const int to = (tid >> 4) << 3;     // 0..120 (o base)
    const int ts = (tid & 15) << 2;     // 0..60  (s base)

    float acc[8][4];
#pragma unroll
    for (int i = 0; i < 8; i++)
#pragma unroll
        for (int j = 0; j < 4; j++) acc[i][j] = 0.f;

    for (int k = 0; k < 8; k++) {
        const int buf = k & 1;
        if (k < 7)   // prefetch next X chunk
            xr = *(const float4*)(X + (size_t)((k + 1) * 16 + xc) * HW + s0 + xs);

        const float* Wc = Wt + k * 16 * 128;
        const float* Xc = Xt + buf * 1024;
#pragma unroll
        for (int c = 0; c < 16; c++) {
            const float4 a0 = *(const float4*)(Wc + c * 128 + to);
            const float4 a1 = *(const float4*)(Wc + c * 128 + to + 4);
            const float4 x0 = *(const float4*)(Xc + c * 64 + ts);
            const float av[8] = {a0.x, a0.y, a0.z, a0.w, a1.x, a1.y, a1.z, a1.w};
            const float xv[4] = {x0.x, x0.y, x0.z, x0.w};
#pragma unroll
            for (int i = 0; i < 8; i++)
#pragma unroll
                for (int j = 0; j < 4; j++)
                    acc[i][j] += av[i] * xv[j];
        }
        if (k < 7)
            *(float4*)&Xt[(buf ^ 1) * 1024 + xc * 64 + xs] = xr;
        __syncthreads();
    }

    float* Ob = OUT + (size_t)(b * 128 + to) * HW + s0 + ts;
#pragma unroll
    for (int i = 0; i < 8; i++)
        *(float4*)(Ob + (size_t)i * HW) =
            make_float4(acc[i][0], acc[i][1], acc[i][2], acc[i][3]);
}

// ---------------------------------------------------------------------------
// Kernel 2: fused window attention + row/col refine.
// 16x16 spatial tile -> 256 blocks of 256 threads: a SINGLE wave at
// 2 blocks/SM (vs 512 blocks / 1.15 super-waves before = 58% timeline
// utilization). 16 warps/SM. Compact code (runtime outer loops + unrolled
// 7-tap inner), direct-exp softmax, K fp32 / V fp16 in smem (86.8KB).
// ---------------------------------------------------------------------------
#define HR 30
#define HC 30
#define C4STR (HR * HC)       // 900
#define KT4   (4 * C4STR)     // 3600 float4 (K, 4 ch-quad planes)
#define VT4   (2 * C4STR)     // 1800 uint4  (V, 2 ch-octet half8 planes)

// one attention tap: score = <q,k16> + rel; p = exp(score); l += p; a += p*V
__device__ __forceinline__ void tap16(
    int off, float rel, float& l, float* a,
    const float4* __restrict__ Kt, const uint4* __restrict__ Vt,
    const float* q)
{
    const float4 k0 = Kt[off];
    const float4 k1 = Kt[C4STR + off];
    const float4 k2 = Kt[2 * C4STR + off];
    const float4 k3 = Kt[3 * C4STR + off];
    float s = rel;
    s += q[0]  * k0.x + q[1]  * k0.y + q[2]  * k0.z + q[3]  * k0.w;
    s += q[4]  * k1.x + q[5]  * k1.y + q[6]  * k1.z + q[7]  * k1.w;
    s += q[8]  * k2.x + q[9]  * k2.y + q[10] * k2.z + q[11] * k2.w;
    s += q[12] * k3.x + q[13] * k3.y + q[14] * k3.z + q[15] * k3.w;
    const float p = __expf(s);
    l += p;
    const uint4 va = Vt[off];
    const uint4 vb = Vt[C4STR + off];
    const float2 f0 = __half22float2(*(const __half2*)&va.x);
    const float2 f1 = __half22float2(*(const __half2*)&va.y);
    const float2 f2 = __half22float2(*(const __half2*)&va.z);
    const float2 f3 = __half22float2(*(const __half2*)&va.w);
    const float2 f4 = __half22float2(*(const __half2*)&vb.x);
    const float2 f5 = __half22float2(*(const __half2*)&vb.y);
    const float2 f6 = __half22float2(*(const __half2*)&vb.z);
    const float2 f7 = __half22float2(*(const __half2*)&vb.w);
    a[0]  += p * f0.x;  a[1]  += p * f0.y;
    a[2]  += p * f1.x;  a[3]  += p * f1.y;
    a[4]  += p * f2.x;  a[5]  += p * f2.y;
    a[6]  += p * f3.x;  a[7]  += p * f3.y;
    a[8]  += p * f4.x;  a[9]  += p * f4.y;
    a[10] += p * f5.x;  a[11] += p * f5.y;
    a[12] += p * f6.x;  a[13] += p * f6.y;
    a[14] += p * f7.x;  a[15] += p * f7.y;
}

__global__ __launch_bounds__(256, 2) void attn_kernel(
    const float* __restrict__ rel_h,
    const float* __restrict__ rel_w,
    float* __restrict__ out)
{
    extern __shared__ float4 sm4[];
    float4* Kt  = sm4;                          // fp32 K: 4 planes x 900
    uint4*  Vt  = (uint4*)(sm4 + KT4);          // fp16 V: 2 planes x 900
    float* rels = (float*)(sm4 + KT4 + VT4);    // [16*7]

    const int tid = threadIdx.x;                // 256 threads
    const int tx = tid & 15, ty = tid >> 4;     // 16w x 16h tile
    const int w0 = blockIdx.x << 4;             // 4 tiles of 16
    const int h0 = blockIdx.y << 4;             // 4 tiles of 16
    const int b  = blockIdx.z >> 3;
    const int g  = blockIdx.z & 7;
    const int cb = g << 4;

    if (tid < 112) {
        const int c = tid / 7, i = tid % 7;
        rels[tid] = (g < 4) ? rel_h[(cb + c) * 7 + i]
                            : rel_w[(cb + c - 64) * 7 + i];
    }

    const float* Kg = g_K + (size_t)(b * 128 + cb) * HW;
    const float* Vg = g_V + (size_t)(b * 128 + cb) * HW;

    // K tile: fp32, 4 channel-quad planes (zero outside image = padding)
    for (int idx = tid; idx < KT4; idx += 256) {
        const int c4  = idx / C4STR;
        const int rem = idx - c4 * C4STR;
        const int r   = rem / HC;
        const int cc  = rem - r * HC;
        const int h = h0 - 7 + r;
        const int w = w0 - 7 + cc;
        float4 kv = make_float4(0.f, 0.f, 0.f, 0.f);
        if ((unsigned)h < 64u && (unsigned)w < 64u) {
            const size_t base = (size_t)(c4 * 4) * HW + h * 64 + w;
            kv.x = Kg[base];          kv.y = Kg[base + HW];
            kv.z = Kg[base + 2 * HW]; kv.w = Kg[base + 3 * HW];
        }
        Kt[idx] = kv;
    }
    // V tile: fp16 half2-packed, 2 channel-octet planes
    for (int idx = tid; idx < VT4; idx += 256) {
        const int p   = idx / C4STR;            // 0: ch0-7, 1: ch8-15
        const int rem = idx - p * C4STR;
        const int r   = rem / HC;
        const int cc  = rem - r * HC;
        const int h = h0 - 7 + r;
        const int w = w0 - 7 + cc;
        uint4 u = make_uint4(0u, 0u, 0u, 0u);
        if ((unsigned)h < 64u && (unsigned)w < 64u) {
            const size_t base = (size_t)(p * 8) * HW + h * 64 + w;
            __half2 h0v = __floats2half2_rn(Vg[base],          Vg[base + HW]);
            __half2 h1v = __floats2half2_rn(Vg[base + 2 * HW], Vg[base + 3 * HW]);
            __half2 h2v = __floats2half2_rn(Vg[base + 4 * HW], Vg[base + 5 * HW]);
            __half2 h3v = __floats2half2_rn(Vg[base + 6 * HW], Vg[base + 7 * HW]);
            u.x = *(unsigned*)&h0v; u.y = *(unsigned*)&h1v;
            u.z = *(unsigned*)&h2v; u.w = *(unsigned*)&h3v;
        }
        Vt[idx] = u;
    }
    __syncthreads();

    const int h = h0 + ty, w = w0 + tx;

    float q[16];
    const float* Qg = g_Q + (size_t)(b * 128 + cb) * HW + h * 64 + w;
#pragma unroll
    for (int c = 0; c < 16; c++) q[c] = Qg[(size_t)c * HW];

    // rel bias scores in registers (this loop is fully unrolled: tiny)
    float rp[7];
#pragma unroll
    for (int i = 0; i < 7; i++) {
        float s = 0.f;
#pragma unroll
        for (int c = 0; c < 16; c++) s += q[c] * rels[c * 7 + i];
        rp[i] = s;
    }

    float outv[16];
#pragma unroll
    for (int c = 0; c < 16; c++) outv[c] = 0.f;

    float l;
    float a[16];

    // ---- main 7x7 window (score = <q,k> + rel) ----
    // rel-indexed dim on the inner UNROLLED loop -> rp[] static indexing;
    // outer loop kept runtime (#pragma unroll 1) for compact code.
    l = 0.f;
#pragma unroll
    for (int c = 0; c < 16; c++) a[c] = 0.f;
    if (g < 4) {
        // rel indexed by window row i -> inner loop over i (stride HC)
#pragma unroll 1
        for (int j = 0; j < 7; j++) {
            const int off0 = (ty + 4) * HC + (tx + 4 + j);
#pragma unroll
            for (int i = 0; i < 7; i++)
                tap16(off0 + i * HC, rp[i], l, a, Kt, Vt, q);
        }
    } else {
        // rel indexed by window col j -> inner loop over j (stride 1)
#pragma unroll 1
        for (int i = 0; i < 7; i++) {
            const int off0 = (ty + 4 + i) * HC + (tx + 4);
#pragma unroll
            for (int j = 0; j < 7; j++)
                tap16(off0 + j, rp[j], l, a, Kt, Vt, q);
        }
    }
    {
        const float inv = 1.f / l;
#pragma unroll
        for (int c = 0; c < 16; c++) outv[c] += a[c] * inv;
    }

    // ---- row refine: 15 taps along w ----
    l = 0.f;
#pragma unroll
    for (int c = 0; c < 16; c++) a[c] = 0.f;
#pragma unroll 1
    for (int t = 0; t < 15; t++)
        tap16((ty + 7) * HC + (tx + t), 0.f, l, a, Kt, Vt, q);
    {
        const float inv = 1.f / l;
#pragma unroll
        for (int c = 0; c < 16; c++) outv[c] += a[c] * inv;
    }

    // ---- col refine: 15 taps along h ----
    l = 0.f;
#pragma unroll
    for (int c = 0; c < 16; c++) a[c] = 0.f;
#pragma unroll 1
    for (int t = 0; t < 15; t++)
        tap16((ty + t) * HC + (tx + 7), 0.f, l, a, Kt, Vt, q);
    {
        const float inv = 1.f / l;
#pragma unroll
        for (int c = 0; c < 16; c++) outv[c] += a[c] * inv;
    }

    float* Og = out + (size_t)(b * 128 + cb) * HW + h * 64 + w;
#pragma unroll
    for (int c = 0; c < 16; c++) Og[(size_t)c * HW] = outv[c];
}

// ---------------------------------------------------------------------------
extern "C" void kernel_launch(void* const* d_in, const int* in_sizes, int n_in,
                              void* d_out, int out_size)
{
    const float* fm = (const float*)d_in[0];
    const float* wq = (const float*)d_in[1];
    const float* wk = (const float*)d_in[2];
    const float* wv = (const float*)d_in[3];
    const float* rh = (const float*)d_in[4];
    const float* rw = (const float*)d_in[5];
    float* out = (float*)d_out;

    cudaFuncSetAttribute(qkv_kernel,  cudaFuncAttributeMaxDynamicSharedMemorySize, 73728);
    cudaFuncSetAttribute(attn_kernel, cudaFuncAttributeMaxDynamicSharedMemorySize, 90112);
    cudaFuncSetAttribute(qkv_kernel,  cudaFuncAttributePreferredSharedMemoryCarveout, 100);
    cudaFuncSetAttribute(attn_kernel, cudaFuncAttributePreferredSharedMemoryCarveout, 100);

    qkv_kernel<<<dim3(64, 3, 2), 256, 73728>>>(fm, wq, wk, wv);

    // K fp32 (57600B) + V fp16 (28800B) + rels (448B) = 86848B -> 2 blocks/SM
    const int attn_smem = KT4 * 16 + VT4 * 16 + 112 * 4;
    attn_kernel<<<dim3(4, 4, 16), 256, attn_smem>>>(rh, rw, out);
}

// round 17
// speedup vs baseline: 1.4535x; 1.0450x over previous
#include <cuda_runtime.h>
#include <cuda_fp16.h>

#define HW 4096

// Scratch: Q, K, V maps (B=2, C=128, H*W=4096), fp32
__device__ float g_Q[2 * 128 * HW];
__device__ float g_K[2 * 128 * HW];
__device__ float g_V[2 * 128 * HW];

// ---- packed f32x2 helpers (FFMA2: 2 fp32 FMA per issue slot; PTX-only) ----
__device__ __forceinline__ unsigned long long pk2(float lo, float hi)
{
    unsigned long long r;
    asm("mov.b64 %0, {%1, %2};" : "=l"(r) : "f"(lo), "f"(hi));
    return r;
}
__device__ __forceinline__ void upk2(float& lo, float& hi, unsigned long long v)
{
    asm("mov.b64 {%0, %1}, %2;" : "=f"(lo), "=f"(hi) : "l"(v));
}
__device__ __forceinline__ unsigned long long fma2(
    unsigned long long a, unsigned long long b, unsigned long long c)
{
    unsigned long long d;
    asm("fma.rn.f32x2 %0, %1, %2, %3;" : "=l"(d) : "l"(a), "l"(b), "l"(c));
    return d;
}

// ---------------------------------------------------------------------------
// Kernel 1: fused 1x1-conv GEMMs.  out[o,s] = sum_c W[c,o] * X[c,s]
// ot: 0 -> Q (wq, fm_t1), 1 -> K (wk, fm_t0), 2 -> V (wv, fm_t0).
// Block tile 128o x 64s -> 384 blocks, 256 thr, 8x4 microtile in f32x2:
// W row-pairs come free from the float4 smem loads (ulonglong2 views),
// X is broadcast-packed (4 movs per c) -> 16 FFMA2 + 4 movs + 3 LDS per c
// instead of 32 FFMA + 3 LDS: ~1.5x fewer issue slots, 2x FLOP/slot.
// ---------------------------------------------------------------------------
__global__ __launch_bounds__(256, 3) void qkv_kernel(
    const float* __restrict__ fm,
    const float* __restrict__ wq,
    const float* __restrict__ wk,
    const float* __restrict__ wv)
{
    extern __shared__ float sm[];
    float* Wt = sm;                   // [c][o] : 128*128
    float* Xt = sm + 16384;           // [2][16][64]  (also transpose staging)

    const int tid = threadIdx.x;
    const int ot  = blockIdx.y;        // 0..2
    const int b   = blockIdx.z;        // 0..1
    const int s0  = blockIdx.x << 6;   // 64 stiles of 64

    const float* Wg = (ot == 0) ? wq : (ot == 1) ? wk : wv;
    const float* X  = fm + (size_t)(b * 256 + (ot == 0 ? 128 : 0)) * HW;
    float* OUT      = (ot == 0) ? g_Q : (ot == 1) ? g_K : g_V;

    // ---- inline transpose: W[o][c] (global) -> Wt[c][o] (smem) ----
    {
        const int ttx = tid & 31;          // lane
        const int tty = tid >> 5;          // warp 0..7
        float* st0 = Xt;                   // 32x32 swizzled
        float* st1 = Xt + 1024;
        for (int it = 0; it < 8; it++) {
#pragma unroll
            for (int p = 0; p < 2; p++) {
                const int st = it * 2 + p;
                const int bo = (st >> 2) << 5;   // o tile base
                const int bc = (st & 3) << 5;    // c tile base
                float* stg = p ? st1 : st0;
#pragma unroll
                for (int i = 0; i < 4; i++) {
                    const int r = tty * 4 + i;   // o_local
                    stg[r * 32 + (ttx ^ r)] = Wg[(bo + r) * 128 + bc + ttx];
                }
            }
            __syncthreads();
#pragma unroll
            for (int p = 0; p < 2; p++) {
                const int st = it * 2 + p;
                const int bo = (st >> 2) << 5;
                const int bc = (st & 3) << 5;
                const float* stg = p ? st1 : st0;
#pragma unroll
                for (int i = 0; i < 4; i++) {
                    const int cl = tty * 4 + i;  // c_local
                    Wt[(bc + cl) * 128 + bo + ttx] = stg[ttx * 32 + (cl ^ ttx)];
                }
            }
            __syncthreads();
        }
    }

    // X chunk-load coordinates (one float4 per thread per chunk)
    const int xc = tid >> 4;            // 0..15 (c within chunk)
    const int xs = (tid & 15) << 2;     // 0..60 (s quad)

    float4 xr = *(const float4*)(X + (size_t)xc * HW + s0 + xs);
    *(float4*)&Xt[xc * 64 + xs] = xr;
    __syncthreads();

    const int to = (tid >> 4) << 3;     // 0..120 (o base)
    const int ts = (tid & 15) << 2;     // 0..60  (s base)

    // acc2[ip][j]: packed rows (to+2ip, to+2ip+1) x col j
    unsigned long long acc2[4][4];
#pragma unroll
    for (int i = 0; i < 4; i++)
#pragma unroll
        for (int j = 0; j < 4; j++) acc2[i][j] = 0ull;   // (0.f, 0.f)

    for (int k = 0; k < 8; k++) {
        const int buf = k & 1;
        if (k < 7)   // prefetch next X chunk
            xr = *(const float4*)(X + (size_t)((k + 1) * 16 + xc) * HW + s0 + xs);

        const float* Wc = Wt + k * 16 * 128;
        const float* Xc = Xt + buf * 1024;
#pragma unroll
        for (int c = 0; c < 16; c++) {
            const ulonglong2 ap0 = *(const ulonglong2*)(Wc + c * 128 + to);
            const ulonglong2 ap1 = *(const ulonglong2*)(Wc + c * 128 + to + 4);
            const float4 x0 = *(const float4*)(Xc + c * 64 + ts);
            const unsigned long long xb0 = pk2(x0.x, x0.x);
            const unsigned long long xb1 = pk2(x0.y, x0.y);
            const unsigned long long xb2 = pk2(x0.z, x0.z);
            const unsigned long long xb3 = pk2(x0.w, x0.w);
            acc2[0][0] = fma2(ap0.x, xb0, acc2[0][0]);
            acc2[0][1] = fma2(ap0.x, xb1, acc2[0][1]);
            acc2[0][2] = fma2(ap0.x, xb2, acc2[0][2]);
            acc2[0][3] = fma2(ap0.x, xb3, acc2[0][3]);
            acc2[1][0] = fma2(ap0.y, xb0, acc2[1][0]);
            acc2[1][1] = fma2(ap0.y, xb1, acc2[1][1]);
            acc2[1][2] = fma2(ap0.y, xb2, acc2[1][2]);
            acc2[1][3] = fma2(ap0.y, xb3, acc2[1][3]);
            acc2[2][0] = fma2(ap1.x, xb0, acc2[2][0]);
            acc2[2][1] = fma2(ap1.x, xb1, acc2[2][1]);
            acc2[2][2] = fma2(ap1.x, xb2, acc2[2][2]);
            acc2[2][3] = fma2(ap1.x, xb3, acc2[2][3]);
            acc2[3][0] = fma2(ap1.y, xb0, acc2[3][0]);
            acc2[3][1] = fma2(ap1.y, xb1, acc2[3][1]);
            acc2[3][2] = fma2(ap1.y, xb2, acc2[3][2]);
            acc2[3][3] = fma2(ap1.y, xb3, acc2[3][3]);
        }
        if (k < 7)
            *(float4*)&Xt[(buf ^ 1) * 1024 + xc * 64 + xs] = xr;
        __syncthreads();
    }

    float* Ob = OUT + (size_t)(b * 128 + to) * HW + s0 + ts;
#pragma unroll
    for (int ip = 0; ip < 4; ip++) {
        float r0[4], r1[4];
#pragma unroll
        for (int j = 0; j < 4; j++) upk2(r0[j], r1[j], acc2[ip][j]);
        *(float4*)(Ob + (size_t)(2 * ip) * HW)     = make_float4(r0[0], r0[1], r0[2], r0[3]);
        *(float4*)(Ob + (size_t)(2 * ip + 1) * HW) = make_float4(r1[0], r1[1], r1[2], r1[3]);
    }
}

// ---------------------------------------------------------------------------
// Kernel 2: fused window attention + row/col refine.
// 16x16 spatial tile, 256 blocks (single wave at 2 blocks/SM), compact code
// (runtime outer loops + unrolled 7-tap inner). Dot product in f32x2: q
// packed once, K read as ulonglong2 pairs (same LDS.128) -> 8 FFMA2 + 1
// unpack + 1 add per tap instead of 16 FFMA. V fp16, scalar accumulate.
// Direct-exp softmax (shift-invariant; validated).
// ---------------------------------------------------------------------------
#define HR 30
#define HC 30
#define C4STR (HR * HC)       // 900
#define KT4   (4 * C4STR)     // 3600 float4 (K, 4 ch-quad planes)
#define VT4   (2 * C4STR)     // 1800 uint4  (V, 2 ch-octet half8 planes)

// one attention tap: score = <q,k16> + rel; p = exp(score); l += p; a += p*V
__device__ __forceinline__ void tap16(
    int off, float rel, float& l, float* a,
    const ulonglong2* __restrict__ Kp, const uint4* __restrict__ Vt,
    const unsigned long long* q2)
{
    const ulonglong2 kp0 = Kp[off];
    const ulonglong2 kp1 = Kp[C4STR + off];
    const ulonglong2 kp2 = Kp[2 * C4STR + off];
    const ulonglong2 kp3 = Kp[3 * C4STR + off];
    unsigned long long s2 = 0ull;
    s2 = fma2(q2[0], kp0.x, s2);
    s2 = fma2(q2[1], kp0.y, s2);
    s2 = fma2(q2[2], kp1.x, s2);
    s2 = fma2(q2[3], kp1.y, s2);
    s2 = fma2(q2[4], kp2.x, s2);
    s2 = fma2(q2[5], kp2.y, s2);
    s2 = fma2(q2[6], kp3.x, s2);
    s2 = fma2(q2[7], kp3.y, s2);
    float slo, shi;
    upk2(slo, shi, s2);
    const float p = __expf(slo + shi + rel);
    l += p;
    const uint4 va = Vt[off];
    const uint4 vb = Vt[C4STR + off];
    const float2 f0 = __half22float2(*(const __half2*)&va.x);
    const float2 f1 = __half22float2(*(const __half2*)&va.y);
    const float2 f2 = __half22float2(*(const __half2*)&va.z);
    const float2 f3 = __half22float2(*(const __half2*)&va.w);
    const float2 f4 = __half22float2(*(const __half2*)&vb.x);
    const float2 f5 = __half22float2(*(const __half2*)&vb.y);
    const float2 f6 = __half22float2(*(const __half2*)&vb.z);
    const float2 f7 = __half22float2(*(const __half2*)&vb.w);
    a[0]  += p * f0.x;  a[1]  += p * f0.y;
    a[2]  += p * f1.x;  a[3]  += p * f1.y;
    a[4]  += p * f2.x;  a[5]  += p * f2.y;
    a[6]  += p * f3.x;  a[7]  += p * f3.y;
    a[8]  += p * f4.x;  a[9]  += p * f4.y;
    a[10] += p * f5.x;  a[11] += p * f5.y;
    a[12] += p * f6.x;  a[13] += p * f6.y;
    a[14] += p * f7.x;  a[15] += p * f7.y;
}

__global__ __launch_bounds__(256, 2) void attn_kernel(
    const float* __restrict__ rel_h,
    const float* __restrict__ rel_w,
    float* __restrict__ out)
{
    extern __shared__ float4 sm4[];
    float4* Kt  = sm4;                          // fp32 K: 4 planes x 900
    uint4*  Vt  = (uint4*)(sm4 + KT4);          // fp16 V: 2 planes x 900
    float* rels = (float*)(sm4 + KT4 + VT4);    // [16*7]

    const int tid = threadIdx.x;                // 256 threads
    const int tx = tid & 15, ty = tid >> 4;     // 16w x 16h tile
    const int w0 = blockIdx.x << 4;             // 4 tiles of 16
    const int h0 = blockIdx.y << 4;             // 4 tiles of 16
    const int b  = blockIdx.z >> 3;
    const int g  = blockIdx.z & 7;
    const int cb = g << 4;

    if (tid < 112) {
        const int c = tid / 7, i = tid % 7;
        rels[tid] = (g < 4) ? rel_h[(cb + c) * 7 + i]
                            : rel_w[(cb + c - 64) * 7 + i];
    }

    const float* Kg = g_K + (size_t)(b * 128 + cb) * HW;
    const float* Vg = g_V + (size_t)(b * 128 + cb) * HW;

    // K tile: fp32, 4 channel-quad planes (zero outside image = padding)
    for (int idx = tid; idx < KT4; idx += 256) {
        const int c4  = idx / C4STR;
        const int rem = idx - c4 * C4STR;
        const int r   = rem / HC;
        const int cc  = rem - r * HC;
        const int h = h0 - 7 + r;
        const int w = w0 - 7 + cc;
        float4 kv = make_float4(0.f, 0.f, 0.f, 0.f);
        if ((unsigned)h < 64u && (unsigned)w < 64u) {
            const size_t base = (size_t)(c4 * 4) * HW + h * 64 + w;
            kv.x = Kg[base];          kv.y = Kg[base + HW];
            kv.z = Kg[base + 2 * HW]; kv.w = Kg[base + 3 * HW];
        }
        Kt[idx] = kv;
    }
    // V tile: fp16 half2-packed, 2 channel-octet planes
    for (int idx = tid; idx < VT4; idx += 256) {
        const int p   = idx / C4STR;            // 0: ch0-7, 1: ch8-15
        const int rem = idx - p * C4STR;
        const int r   = rem / HC;
        const int cc  = rem - r * HC;
        const int h = h0 - 7 + r;
        const int w = w0 - 7 + cc;
        uint4 u = make_uint4(0u, 0u, 0u, 0u);
        if ((unsigned)h < 64u && (unsigned)w < 64u) {
            const size_t base = (size_t)(p * 8) * HW + h * 64 + w;
            __half2 h0v = __floats2half2_rn(Vg[base],          Vg[base + HW]);
            __half2 h1v = __floats2half2_rn(Vg[base + 2 * HW], Vg[base + 3 * HW]);
            __half2 h2v = __floats2half2_rn(Vg[base + 4 * HW], Vg[base + 5 * HW]);
            __half2 h3v = __floats2half2_rn(Vg[base + 6 * HW], Vg[base + 7 * HW]);
            u.x = *(unsigned*)&h0v; u.y = *(unsigned*)&h1v;
            u.z = *(unsigned*)&h2v; u.w = *(unsigned*)&h3v;
        }
        Vt[idx] = u;
    }
    __syncthreads();

    const ulonglong2* Kp = (const ulonglong2*)Kt;

    const int h = h0 + ty, w = w0 + tx;

    float q[16];
    const float* Qg = g_Q + (size_t)(b * 128 + cb) * HW + h * 64 + w;
#pragma unroll
    for (int c = 0; c < 16; c++) q[c] = Qg[(size_t)c * HW];

    // rel bias scores in registers (this loop is fully unrolled: tiny)
    float rp[7];
#pragma unroll
    for (int i = 0; i < 7; i++) {
        float s = 0.f;
#pragma unroll
        for (int c = 0; c < 16; c++) s += q[c] * rels[c * 7 + i];
        rp[i] = s;
    }

    // q packed once into f32x2 pairs matching K's ulonglong2 lanes
    unsigned long long q2[8];
#pragma unroll
    for (int i = 0; i < 8; i++) q2[i] = pk2(q[2 * i], q[2 * i + 1]);

    float outv[16];
#pragma unroll
    for (int c = 0; c < 16; c++) outv[c] = 0.f;

    float l;
    float a[16];

    // ---- main 7x7 window (score = <q,k> + rel) ----
    // rel-indexed dim on the inner UNROLLED loop -> rp[] static indexing;
    // outer loop kept runtime (#pragma unroll 1) for compact code.
    l = 0.f;
#pragma unroll
    for (int c = 0; c < 16; c++) a[c] = 0.f;
    if (g < 4) {
        // rel indexed by window row i -> inner loop over i (stride HC)
#pragma unroll 1
        for (int j = 0; j < 7; j++) {
            const int off0 = (ty + 4) * HC + (tx + 4 + j);
#pragma unroll
            for (int i = 0; i < 7; i++)
                tap16(off0 + i * HC, rp[i], l, a, Kp, Vt, q2);
        }
    } else {
        // rel indexed by window col j -> inner loop over j (stride 1)
#pragma unroll 1
        for (int i = 0; i < 7; i++) {
            const int off0 = (ty + 4 + i) * HC + (tx + 4);
#pragma unroll
            for (int j = 0; j < 7; j++)
                tap16(off0 + j, rp[j], l, a, Kp, Vt, q2);
        }
    }
    {
        const float inv = 1.f / l;
#pragma unroll
        for (int c = 0; c < 16; c++) outv[c] += a[c] * inv;
    }

    // ---- row refine: 15 taps along w ----
    l = 0.f;
#pragma unroll
    for (int c = 0; c < 16; c++) a[c] = 0.f;
#pragma unroll 1
    for (int t = 0; t < 15; t++)
        tap16((ty + 7) * HC + (tx + t), 0.f, l, a, Kp, Vt, q2);
    {
        const float inv = 1.f / l;
#pragma unroll
        for (int c = 0; c < 16; c++) outv[c] += a[c] * inv;
    }

    // ---- col refine: 15 taps along h ----
    l = 0.f;
#pragma unroll
    for (int c = 0; c < 16; c++) a[c] = 0.f;
#pragma unroll 1
    for (int t = 0; t < 15; t++)
        tap16((ty + t) * HC + (tx + 7), 0.f, l, a, Kp, Vt, q2);
    {
        const float inv = 1.f / l;
#pragma unroll
        for (int c = 0; c < 16; c++) outv[c] += a[c] * inv;
    }

    float* Og = out + (size_t)(b * 128 + cb) * HW + h * 64 + w;
#pragma unroll
    for (int c = 0; c < 16; c++) Og[(size_t)c * HW] = outv[c];
}

// ---------------------------------------------------------------------------
extern "C" void kernel_launch(void* const* d_in, const int* in_sizes, int n_in,
                              void* d_out, int out_size)
{
    const float* fm = (const float*)d_in[0];
    const float* wq = (const float*)d_in[1];
    const float* wk = (const float*)d_in[2];
    const float* wv = (const float*)d_in[3];
    const float* rh = (const float*)d_in[4];
    const float* rw = (const float*)d_in[5];
    float* out = (float*)d_out;

    cudaFuncSetAttribute(qkv_kernel,  cudaFuncAttributeMaxDynamicSharedMemorySize, 73728);
    cudaFuncSetAttribute(attn_kernel, cudaFuncAttributeMaxDynamicSharedMemorySize, 90112);
    cudaFuncSetAttribute(qkv_kernel,  cudaFuncAttributePreferredSharedMemoryCarveout, 100);
    cudaFuncSetAttribute(attn_kernel, cudaFuncAttributePreferredSharedMemoryCarveout, 100);

    qkv_kernel<<<dim3(64, 3, 2), 256, 73728>>>(fm, wq, wk, wv);

    // K fp32 (57600B) + V fp16 (28800B) + rels (448B) = 86848B -> 2 blocks/SM
    const int attn_smem = KT4 * 16 + VT4 * 16 + 112 * 4;
    attn_kernel<<<dim3(4, 4, 16), 256, attn_smem>>>(rh, rw, out);
}